// round 1
// baseline (speedup 1.0000x reference)
#include <cuda_runtime.h>

// RoIAlign, matching the JAX reference:
//   features: (B=2, C=256, H=200, W=200) fp32
//   rois:     (N=512, 5)  [batch_idx, x1, y1, x2, y2] in image coords
//   out:      (N, C, 7, 7) fp32
// POOLED 7x7, spatial_scale 1/16, sampling_ratio 2, mean over 4 samples,
// per-axis boundary logic identical to the reference _interp_axis.

#define POOLED_H 7
#define POOLED_W 7
#define SAMP 2
#define SPATIAL_SCALE 0.0625f

__global__ __launch_bounds__(256)
void roi_align_kernel(const float* __restrict__ feat,
                      const float* __restrict__ rois,
                      float* __restrict__ out,
                      int N, int C, int H, int W)
{
    int idx = blockIdx.x * blockDim.x + threadIdx.x;
    int total = N * C * POOLED_H * POOLED_W;
    if (idx >= total) return;

    // idx = ((n*C + c)*POOLED_H + ph)*POOLED_W + pw   (pw fastest -> spatial coalescing)
    int pw = idx % POOLED_W;
    int ph = (idx / POOLED_W) % POOLED_H;
    int c  = (idx / (POOLED_W * POOLED_H)) % C;
    int n  = idx / (POOLED_W * POOLED_H * C);

    const float* r = rois + n * 5;
    int   b  = (int)r[0];
    float x1 = r[1] * SPATIAL_SCALE;
    float y1 = r[2] * SPATIAL_SCALE;
    float x2 = r[3] * SPATIAL_SCALE;
    float y2 = r[4] * SPATIAL_SCALE;

    float roi_w = fmaxf(x2 - x1, 1.0f);
    float roi_h = fmaxf(y2 - y1, 1.0f);
    float bin_w = roi_w * (1.0f / POOLED_W);
    float bin_h = roi_h * (1.0f / POOLED_H);

    const float* fc = feat + ((size_t)b * C + c) * (size_t)(H * W);

    float acc = 0.0f;

    #pragma unroll
    for (int iy = 0; iy < SAMP; iy++) {
        float yc = y1 + (ph + (iy + 0.5f) * (1.0f / SAMP)) * bin_h;
        bool  vy = (yc >= -1.0f) && (yc <= (float)H);
        float cy = fmaxf(yc, 0.0f);
        int   yl = min((int)floorf(cy), H - 1);
        int   yh = min(yl + 1, H - 1);
        float fy = (yl >= H - 1) ? 0.0f : (cy - (float)yl);

        #pragma unroll
        for (int ix = 0; ix < SAMP; ix++) {
            float xc = x1 + (pw + (ix + 0.5f) * (1.0f / SAMP)) * bin_w;
            bool  vx = (xc >= -1.0f) && (xc <= (float)W);
            float cx = fmaxf(xc, 0.0f);
            int   xl = min((int)floorf(cx), W - 1);
            int   xh = min(xl + 1, W - 1);
            float fx = (xl >= W - 1) ? 0.0f : (cx - (float)xl);

            if (vy && vx) {
                const float* row_l = fc + (size_t)yl * W;
                const float* row_h = fc + (size_t)yh * W;
                float v00 = __ldg(row_l + xl);
                float v01 = __ldg(row_l + xh);
                float v10 = __ldg(row_h + xl);
                float v11 = __ldg(row_h + xh);
                float top = v00 + fx * (v01 - v00);
                float bot = v10 + fx * (v11 - v10);
                acc += top + fy * (bot - top);
            }
        }
    }

    out[idx] = acc * (1.0f / (SAMP * SAMP));
}

extern "C" void kernel_launch(void* const* d_in, const int* in_sizes, int n_in,
                              void* d_out, int out_size)
{
    const float* feat = (const float*)d_in[0];   // (2,256,200,200) fp32
    const float* rois = (const float*)d_in[1];   // (512,5) fp32
    float* out = (float*)d_out;                  // (512,256,7,7) fp32

    const int B = 2, C = 256, H = 200, W = 200;
    // N derived from rois element count (5 per roi)
    int N = in_sizes[1] / 5;
    (void)B; (void)n_in; (void)out_size;

    int total = N * C * POOLED_H * POOLED_W;
    int threads = 256;
    int blocks = (total + threads - 1) / threads;
    roi_align_kernel<<<blocks, threads>>>(feat, rois, out, N, C, H, W);
}